// round 2
// baseline (speedup 1.0000x reference)
#include <cuda_runtime.h>

// ---------------------------------------------------------------------------
// ShiftSpecificCrossAttention, algebraically restructured:
//   QW[r,:]     = scale * (Q[s,h,:] folded through Wk)        r = h*8+s, 64x512
//   logits      = enc @ QW^T + qb + dist*cos, masked
//   ctx[b,r,:]  = softmax(logits) @ enc        (AV order swapped vs reference)
//   tmp2        = per-head ctx @ Wv_h^T + bv   (bv exact: softmax rows sum to 1)
//   out         = tmp2 @ Wo^T (+bo +shift, LayerNorm, any_valid mask)
// ~17.2 GMAC total; enc (256MB) read from HBM exactly once.
// Inner loops use packed fp32x2 FMA (fma.rn.f32x2) -> 2x fma-pipe throughput.
// ---------------------------------------------------------------------------

#define D_MODEL   512
#define N_SHIFTS  8
#define N_HEADS   8
#define HEAD_DIM  64
#define B_SZ      2048
#define K_NBR     64
#define SH        64
#define SCALE     0.125f
#define LN_EPS    1e-5f

#define ENC_PITCH 516            // floats; /4=129 odd -> conflict-free LDS.128
#define QW_PITCH  132            // 128-col chunk + pad; /4=33 odd
#define ATT_PITCH 65
#define A2_PITCH  66             // float2 units
#define T2_PITCH  516
#define CT_PITCH  68             // /4=17 odd, %4==0 for LDS.128
#define WT_PITCH  68
#define ROWB      32

typedef unsigned long long u64;

// packed fp32x2 fma: acc = a*b + acc (per 32-bit lane)
#define FMA2(acc, a, b) \
    asm("fma.rn.f32x2 %0, %1, %2, %0;" : "+l"(acc) : "l"(a), "l"(b))

__device__ __forceinline__ float sum2(u64 v) {
    float2 f; asm("mov.b64 {%0,%1}, %2;" : "=f"(f.x), "=f"(f.y) : "l"(v));
    return f.x + f.y;
}

// Scratch (device globals: allocation-free per harness rules)
__device__ __align__(16) float g_Q[N_SHIFTS * D_MODEL];
__device__ __align__(16) float g_QW[SH * D_MODEL];
__device__ float g_qb[SH];
__device__ float g_anyvalid[B_SZ];
__device__ __align__(16) float g_ctx[(size_t)B_SZ * SH * D_MODEL];   // 256 MB

// ---------------------------------------------------------------------------
// A1: Q[s,i] = bq[i] + shift[s,:] . Wq[i,:]
// ---------------------------------------------------------------------------
__global__ void qproj_kernel(const float* __restrict__ shift,
                             const float* __restrict__ Wq,
                             const float* __restrict__ bq) {
    int g = blockIdx.x * blockDim.x + threadIdx.x;
    if (g >= N_SHIFTS * D_MODEL) return;
    int s = g / D_MODEL, i = g % D_MODEL;
    const float* sr = shift + s * D_MODEL;
    const float* wr = Wq + (size_t)i * D_MODEL;
    float a0 = 0.f, a1 = 0.f, a2 = 0.f, a3 = 0.f;
    #pragma unroll 4
    for (int d = 0; d < D_MODEL; d += 4) {
        a0 += sr[d + 0] * wr[d + 0];
        a1 += sr[d + 1] * wr[d + 1];
        a2 += sr[d + 2] * wr[d + 2];
        a3 += sr[d + 3] * wr[d + 3];
    }
    g_Q[g] = bq[i] + ((a0 + a1) + (a2 + a3));
}

// ---------------------------------------------------------------------------
// A2: QW[r,:] = scale * sum_hd Q[s,h*64+hd] * Wk[h*64+hd,:]; qb likewise w/ bk
// ---------------------------------------------------------------------------
__global__ void qw_kernel(const float* __restrict__ Wk,
                          const float* __restrict__ bk) {
    __shared__ float Qs[HEAD_DIM];
    int r = blockIdx.x;
    int h = r / N_SHIFTS, s = r % N_SHIFTS;
    int t = threadIdx.x;
    if (t < HEAD_DIM) Qs[t] = g_Q[s * D_MODEL + h * HEAD_DIM + t];
    __syncthreads();
    #pragma unroll
    for (int jj = 0; jj < D_MODEL / 128; jj++) {
        int c = t + jj * 128;
        float acc = 0.f;
        #pragma unroll 8
        for (int hd = 0; hd < HEAD_DIM; hd++)
            acc += Qs[hd] * Wk[(size_t)(h * HEAD_DIM + hd) * D_MODEL + c];
        g_QW[r * D_MODEL + c] = acc * SCALE;
    }
    if (t == 0) {
        float acc = 0.f;
        for (int hd = 0; hd < HEAD_DIM; hd++)
            acc += Qs[hd] * bk[h * HEAD_DIM + hd];
        g_qb[r] = acc * SCALE;
    }
}

// ---------------------------------------------------------------------------
// B: per-batch fused attention. grid=2048, block=512, smem ~184KB.
// ---------------------------------------------------------------------------
__global__ __launch_bounds__(512, 1)
void attn_kernel(const float* __restrict__ enc,
                 const int* __restrict__ valid,
                 const float* __restrict__ dist,
                 const float* __restrict__ cs_ptr) {
    extern __shared__ float sm[];
    float*  enc_s  = sm;                              // 64*516    = 33024
    float*  qwch   = enc_s + 64 * ENC_PITCH;          // 64*132    =  8448
    float2* attn2  = (float2*)qwch;                   // aliases qwch (64*66 f2)
    float*  attn_s = qwch + 64 * QW_PITCH;            // 64*65     =  4160
    float*  bias_s = attn_s + 64 * ATT_PITCH;         // 64
    float*  keep_s = bias_s + 64;                     // 64
    float*  qb_s   = keep_s + 64;                     // 64
    float*  any_s  = qb_s + 64;                       // 1

    const int b = blockIdx.x;
    const int t = threadIdx.x;
    const float cs = cs_ptr[0];

    // ---- stage enc tile + per-k bias/mask ----
    const float4* encg = (const float4*)(enc + (size_t)b * K_NBR * D_MODEL);
    for (int i = t; i < K_NBR * (D_MODEL / 4); i += 512) {
        int k = i >> 7, c4 = i & 127;
        *(float4*)&enc_s[k * ENC_PITCH + c4 * 4] = encg[i];
    }
    if (t < K_NBR) {
        bias_s[t] = dist[b * K_NBR + t] * cs;
        keep_s[t] = (valid[b * K_NBR + t] != 0) ? 1.f : 0.f;
    }
    if (t < SH) qb_s[t] = g_qb[t];
    if (t == 0) any_s[0] = 0.f;
    __syncthreads();
    if (t < K_NBR && keep_s[t] != 0.f) any_s[0] = 1.f;   // benign same-value race

    // ---- logits: thread (k, rg) computes 8 rows hs = rg*8+j, e reused in regs
    const int k  = t & 63;
    const int rg = t >> 6;            // constant per warp -> qw broadcast
    {
        u64 acc2[8];
        #pragma unroll
        for (int j = 0; j < 8; j++) acc2[j] = 0ull;   // bit pattern (0.f, 0.f)

        for (int ch = 0; ch < 4; ch++) {
            // stage QW chunk: 64 rows x 128 cols
            for (int i = t; i < 64 * 32; i += 512) {
                int r = i >> 5, c = i & 31;
                *(float4*)&qwch[r * QW_PITCH + c * 4] =
                    *(const float4*)&g_QW[r * D_MODEL + ch * 128 + c * 4];
            }
            __syncthreads();
            const float* er = enc_s + k * ENC_PITCH + ch * 128;
            const float* qb_row = qwch + rg * 8 * QW_PITCH;
            #pragma unroll 4
            for (int d4 = 0; d4 < 32; d4++) {
                ulonglong2 e2 = *(const ulonglong2*)(er + d4 * 4);
                #pragma unroll
                for (int j = 0; j < 8; j++) {
                    ulonglong2 q2 = *(const ulonglong2*)(qb_row + j * QW_PITCH + d4 * 4);
                    FMA2(acc2[j], q2.x, e2.x);
                    FMA2(acc2[j], q2.y, e2.y);
                }
            }
            __syncthreads();
        }
        float keep = keep_s[k], biask = bias_s[k];
        #pragma unroll
        for (int j = 0; j < 8; j++) {
            int hs = rg * 8 + j;
            float lg = sum2(acc2[j]) + qb_s[hs] + biask;
            attn_s[hs * ATT_PITCH + k] = (keep != 0.f) ? lg : -10000.0f;
        }
    }
    __syncthreads();

    // ---- softmax per row; write splatted (p,p) pairs into attn2 ----
    {
        int w = t >> 5, l = t & 31;
        #pragma unroll
        for (int rr = 0; rr < 4; rr++) {
            int hs = w * 4 + rr;
            float v0 = attn_s[hs * ATT_PITCH + l];
            float v1 = attn_s[hs * ATT_PITCH + l + 32];
            float m = fmaxf(v0, v1);
            #pragma unroll
            for (int o = 16; o > 0; o >>= 1) m = fmaxf(m, __shfl_xor_sync(~0u, m, o));
            float e0 = __expf(v0 - m), e1 = __expf(v1 - m);
            float ssum = e0 + e1;
            #pragma unroll
            for (int o = 16; o > 0; o >>= 1) ssum += __shfl_xor_sync(~0u, ssum, o);
            float inv = 1.f / ssum;
            float p0 = e0 * inv, p1 = e1 * inv;
            attn2[hs * A2_PITCH + l]      = make_float2(p0, p0);
            attn2[hs * A2_PITCH + l + 32] = make_float2(p1, p1);
        }
    }
    __syncthreads();

    // ---- ctx = attn @ enc, in-place over enc tile; 4 rows x 4 cols / thread
    {
        const int c4  = t & 31;           // float4 column within 128-wide block
        const int hs0 = t >> 5;           // 0..15; rows hs0, +16, +32, +48
        const u64* a0 = (const u64*)(attn2 + (hs0     ) * A2_PITCH);
        const u64* a1 = (const u64*)(attn2 + (hs0 + 16) * A2_PITCH);
        const u64* a2 = (const u64*)(attn2 + (hs0 + 32) * A2_PITCH);
        const u64* a3 = (const u64*)(attn2 + (hs0 + 48) * A2_PITCH);
        #pragma unroll 1
        for (int db = 0; db < 4; db++) {
            const int coff = db * 128 + c4 * 4;
            u64 r0a = 0, r0b = 0, r1a = 0, r1b = 0;
            u64 r2a = 0, r2b = 0, r3a = 0, r3b = 0;
            #pragma unroll 4
            for (int kk = 0; kk < K_NBR; kk++) {
                ulonglong2 e2 = *(const ulonglong2*)&enc_s[kk * ENC_PITCH + coff];
                u64 w0 = a0[kk], w1 = a1[kk], w2 = a2[kk], w3 = a3[kk];
                FMA2(r0a, w0, e2.x); FMA2(r0b, w0, e2.y);
                FMA2(r1a, w1, e2.x); FMA2(r1b, w1, e2.y);
                FMA2(r2a, w2, e2.x); FMA2(r2b, w2, e2.y);
                FMA2(r3a, w3, e2.x); FMA2(r3b, w3, e2.y);
            }
            __syncthreads();   // all reads of this column-block done
            ulonglong2 o;
            o.x = r0a; o.y = r0b; *(ulonglong2*)&enc_s[(hs0     ) * ENC_PITCH + coff] = o;
            o.x = r1a; o.y = r1b; *(ulonglong2*)&enc_s[(hs0 + 16) * ENC_PITCH + coff] = o;
            o.x = r2a; o.y = r2b; *(ulonglong2*)&enc_s[(hs0 + 32) * ENC_PITCH + coff] = o;
            o.x = r3a; o.y = r3b; *(ulonglong2*)&enc_s[(hs0 + 48) * ENC_PITCH + coff] = o;
            __syncthreads();
        }
    }

    // ---- write ctx to global ----
    float* ctxb = g_ctx + (size_t)b * SH * D_MODEL;
    for (int i = t; i < SH * (D_MODEL / 4); i += 512) {
        int r = i >> 7, c4 = i & 127;
        *(float4*)&ctxb[r * D_MODEL + c4 * 4] =
            *(const float4*)&enc_s[r * ENC_PITCH + c4 * 4];
    }
    if (t == 0) g_anyvalid[b] = any_s[0];
}

// ---------------------------------------------------------------------------
// C: per 32 (b,s)-rows: tmp2 = blockdiag(Wv).ctx + bv ; out = tmp2 @ Wo^T ;
//    +bo +shift ; LayerNorm ; any_valid mask.  grid=512, block=256.
// ---------------------------------------------------------------------------
__global__ __launch_bounds__(256, 1)
void out_kernel(const float* __restrict__ Wv, const float* __restrict__ bv,
                const float* __restrict__ Wo, const float* __restrict__ bo,
                const float* __restrict__ shift,
                const float* __restrict__ lnw, const float* __restrict__ lnb,
                float* __restrict__ out) {
    extern __shared__ float sm[];
    float* tmp2  = sm;                                   // 32*516
    float* obuf  = tmp2 + ROWB * T2_PITCH;               // 32*516
    float* ctile = obuf + ROWB * T2_PITCH;               // 32*68
    float* wtile = ctile + ROWB * CT_PITCH;              // 64*68

    const int t = threadIdx.x;
    const int rowbase = blockIdx.x * ROWB;
    const int tdiv = t >> 6;        // 0..3 constant per warp-pair -> broadcasts
    const int hd   = t & 63;

    // ---- stage 1: tmp2[r, h*64+hd] = ctx[(b,h,s),:] . Wv[h*64+hd,:] + bv ----
    for (int h = 0; h < N_HEADS; h++) {
        u64 acc2[8];
        #pragma unroll
        for (int jj = 0; jj < 8; jj++) acc2[jj] = 0ull;
        for (int dc = 0; dc < 8; dc++) {
            for (int i = t; i < ROWB * 16; i += 256) {
                int r = i >> 4, d4 = i & 15;
                int g = rowbase + r; int bb = g >> 3; int ss = g & 7;
                *(float4*)&ctile[r * CT_PITCH + d4 * 4] = *(const float4*)
                    &g_ctx[((size_t)bb * SH + h * N_SHIFTS + ss) * D_MODEL + dc * 64 + d4 * 4];
            }
            for (int i = t; i < 64 * 16; i += 256) {
                int r = i >> 4, d4 = i & 15;
                *(float4*)&wtile[r * WT_PITCH + d4 * 4] = *(const float4*)
                    &Wv[(size_t)(h * HEAD_DIM + r) * D_MODEL + dc * 64 + d4 * 4];
            }
            __syncthreads();
            const float* cb = ctile + tdiv * CT_PITCH;
            const float* wb = wtile + hd * WT_PITCH;
            #pragma unroll 2
            for (int d4 = 0; d4 < 16; d4++) {
                ulonglong2 w2 = *(const ulonglong2*)&wb[d4 * 4];
                #pragma unroll
                for (int jj = 0; jj < 8; jj++) {
                    ulonglong2 c2 = *(const ulonglong2*)&cb[jj * 4 * CT_PITCH + d4 * 4];
                    FMA2(acc2[jj], c2.x, w2.x);
                    FMA2(acc2[jj], c2.y, w2.y);
                }
            }
            __syncthreads();
        }
        float bvv = bv[h * HEAD_DIM + hd];
        #pragma unroll
        for (int jj = 0; jj < 8; jj++)
            tmp2[(jj * 4 + tdiv) * T2_PITCH + h * HEAD_DIM + hd] = sum2(acc2[jj]) + bvv;
    }
    __syncthreads();

    // ---- stage 2: obuf[r, cc*64+hd] = tmp2[r,:] . Wo[cc*64+hd,:] ----
    for (int cc = 0; cc < 8; cc++) {
        u64 acc2[8];
        #pragma unroll
        for (int jj = 0; jj < 8; jj++) acc2[jj] = 0ull;
        for (int dc = 0; dc < 8; dc++) {
            for (int i = t; i < 64 * 16; i += 256) {
                int r = i >> 4, d4 = i & 15;
                *(float4*)&wtile[r * WT_PITCH + d4 * 4] = *(const float4*)
                    &Wo[(size_t)(cc * 64 + r) * D_MODEL + dc * 64 + d4 * 4];
            }
            __syncthreads();
            const float* tb = tmp2 + tdiv * T2_PITCH + dc * 64;
            const float* wb = wtile + hd * WT_PITCH;
            #pragma unroll 2
            for (int d4 = 0; d4 < 16; d4++) {
                ulonglong2 w2 = *(const ulonglong2*)&wb[d4 * 4];
                #pragma unroll
                for (int jj = 0; jj < 8; jj++) {
                    ulonglong2 t2 = *(const ulonglong2*)&tb[jj * 4 * T2_PITCH + d4 * 4];
                    FMA2(acc2[jj], t2.x, w2.x);
                    FMA2(acc2[jj], t2.y, w2.y);
                }
            }
            __syncthreads();
        }
        #pragma unroll
        for (int jj = 0; jj < 8; jj++)
            obuf[(jj * 4 + tdiv) * T2_PITCH + cc * 64 + hd] = sum2(acc2[jj]);
    }
    __syncthreads();

    // ---- LayerNorm + residual + mask, one warp per row ----
    {
        int w = t >> 5, l = t & 31;
        #pragma unroll 1
        for (int rr = 0; rr < 4; rr++) {
            int r = w * 4 + rr;
            int g = rowbase + r; int bb = g >> 3; int ss = g & 7;
            const float* ob = obuf + r * T2_PITCH;
            const float* sh = shift + ss * D_MODEL;
            float s1 = 0.f;
            for (int d = l; d < D_MODEL; d += 32)
                s1 += ob[d] + bo[d] + sh[d];
            #pragma unroll
            for (int o = 16; o > 0; o >>= 1) s1 += __shfl_xor_sync(~0u, s1, o);
            float mu = s1 * (1.f / D_MODEL);
            float s2 = 0.f;
            for (int d = l; d < D_MODEL; d += 32) {
                float x = ob[d] + bo[d] + sh[d] - mu;
                s2 += x * x;
            }
            #pragma unroll
            for (int o = 16; o > 0; o >>= 1) s2 += __shfl_xor_sync(~0u, s2, o);
            float inv = rsqrtf(s2 * (1.f / D_MODEL) + LN_EPS);
            float av = g_anyvalid[bb];
            float* og = out + (size_t)g * D_MODEL;
            for (int d = l; d < D_MODEL; d += 32) {
                float x = ob[d] + bo[d] + sh[d];
                og[d] = ((x - mu) * inv * lnw[d] + lnb[d]) * av;
            }
        }
    }
}

// ---------------------------------------------------------------------------
extern "C" void kernel_launch(void* const* d_in, const int* in_sizes, int n_in,
                              void* d_out, int out_size) {
    (void)in_sizes; (void)n_in; (void)out_size;
    const float* enc   = (const float*)d_in[0];
    const int*   valid = (const int*)d_in[1];
    const float* dist  = (const float*)d_in[2];
    const float* shift = (const float*)d_in[3];
    const float* Wq    = (const float*)d_in[4];
    const float* bq    = (const float*)d_in[5];
    const float* Wk    = (const float*)d_in[6];
    const float* bk    = (const float*)d_in[7];
    const float* Wv    = (const float*)d_in[8];
    const float* bv    = (const float*)d_in[9];
    const float* Wo    = (const float*)d_in[10];
    const float* bo    = (const float*)d_in[11];
    const float* lnw   = (const float*)d_in[12];
    const float* lnb   = (const float*)d_in[13];
    const float* cs    = (const float*)d_in[14];

    const int smemB = (64 * ENC_PITCH + 64 * QW_PITCH + 64 * ATT_PITCH + 4 * 64) * 4;
    const int smemC = (2 * ROWB * T2_PITCH + ROWB * CT_PITCH + 64 * WT_PITCH) * 4;
    cudaFuncSetAttribute(attn_kernel, cudaFuncAttributeMaxDynamicSharedMemorySize, smemB);
    cudaFuncSetAttribute(out_kernel,  cudaFuncAttributeMaxDynamicSharedMemorySize, smemC);

    qproj_kernel<<<(N_SHIFTS * D_MODEL + 127) / 128, 128>>>(shift, Wq, bq);
    qw_kernel<<<SH, 128>>>(Wk, bk);
    attn_kernel<<<B_SZ, 512, smemB>>>(enc, valid, dist, cs);
    out_kernel<<<(B_SZ * N_SHIFTS) / ROWB, 256, smemC>>>(Wv, bv, Wo, bo, shift,
                                                         lnw, lnb, (float*)d_out);
}

// round 10
// speedup vs baseline: 1.9159x; 1.9159x over previous
#include <cuda_runtime.h>

// ---------------------------------------------------------------------------
// ShiftSpecificCrossAttention — tensor-core (mma.sync tf32) restructuring.
//   QW[r,:]   = scale*(Q[s,h,:] folded through Wk)          r=h*8+s, 64x512
//   L         = enc @ QW^T + qb + dist*cos, masked          (tf32 mma)
//   P         = softmax(L)                                  (fp32)
//   ctx       = P @ enc                                     (tf32 mma)
//   tmp2      = per-head ctx @ Wv_h^T + bv                  (tf32 mma)
//   out       = tmp2 @ Wo^T ; +bo+shift ; LayerNorm ; mask  (tf32 mma + fp32)
// 17.2 GMAC total; enc read from HBM once per phase use.
// ---------------------------------------------------------------------------

#define D_MODEL   512
#define N_SHIFTS  8
#define N_HEADS   8
#define B_SZ      2048
#define K_NBR     64
#define SH        64
#define SCALE     0.125f
#define LN_EPS    1e-5f

#define EP   516      // enc / tmp2 pitch (floats); 516%32==4 -> conflict-free
#define QP   132      // 128-col chunk pitch
#define PP   68       // P / 64-col chunk pitch
#define ROWB 64       // (b,s) rows per out-CTA

typedef unsigned int u32;

__device__ __forceinline__ float tf32r(float x) {
    float y; asm("cvt.rna.tf32.f32 %0, %1;" : "=f"(y) : "f"(x)); return y;
}
__device__ __forceinline__ float4 tf32r4(float4 v) {
    v.x = tf32r(v.x); v.y = tf32r(v.y); v.z = tf32r(v.z); v.w = tf32r(v.w);
    return v;
}
// C[16x8] += A[16x8] * B[8x8] (row.col, tf32 in, fp32 accum)
__device__ __forceinline__ void mma8(float* c, const u32* a, const u32* b) {
    asm volatile(
        "mma.sync.aligned.m16n8k8.row.col.f32.tf32.tf32.f32 "
        "{%0,%1,%2,%3},{%4,%5,%6,%7},{%8,%9},{%0,%1,%2,%3};"
        : "+f"(c[0]), "+f"(c[1]), "+f"(c[2]), "+f"(c[3])
        : "r"(a[0]), "r"(a[1]), "r"(a[2]), "r"(a[3]), "r"(b[0]), "r"(b[1]));
}

// Scratch (device globals: allocation-free per harness rules)
__device__ __align__(16) float g_Q[N_SHIFTS * D_MODEL];
__device__ __align__(16) float g_QW[SH * D_MODEL];           // tf32-rounded
__device__ float g_qb[SH];
__device__ float g_anyvalid[B_SZ];
__device__ __align__(16) float g_ctx[(size_t)B_SZ * SH * D_MODEL];   // 256 MB

// ---------------------------------------------------------------------------
// A1: Q[s,i] = bq[i] + shift[s,:] . Wq[i,:]
// ---------------------------------------------------------------------------
__global__ void qproj_kernel(const float* __restrict__ shift,
                             const float* __restrict__ Wq,
                             const float* __restrict__ bq) {
    int gidx = blockIdx.x * blockDim.x + threadIdx.x;
    if (gidx >= N_SHIFTS * D_MODEL) return;
    int s = gidx / D_MODEL, i = gidx % D_MODEL;
    const float* sr = shift + s * D_MODEL;
    const float* wr = Wq + (size_t)i * D_MODEL;
    float a0 = 0.f, a1 = 0.f, a2 = 0.f, a3 = 0.f;
    #pragma unroll 4
    for (int d = 0; d < D_MODEL; d += 4) {
        a0 += sr[d + 0] * wr[d + 0];
        a1 += sr[d + 1] * wr[d + 1];
        a2 += sr[d + 2] * wr[d + 2];
        a3 += sr[d + 3] * wr[d + 3];
    }
    g_Q[gidx] = bq[i] + ((a0 + a1) + (a2 + a3));
}

// ---------------------------------------------------------------------------
// A2: QW[r,:] = scale * sum_hd Q[s,h*64+hd]*Wk[h*64+hd,:]  (tf32-rounded)
// ---------------------------------------------------------------------------
__global__ void qw_kernel(const float* __restrict__ Wk,
                          const float* __restrict__ bk) {
    __shared__ float Qs[64];
    int r = blockIdx.x;
    int h = r / N_SHIFTS, s = r % N_SHIFTS;
    int t = threadIdx.x;
    if (t < 64) Qs[t] = g_Q[s * D_MODEL + h * 64 + t];
    __syncthreads();
    #pragma unroll
    for (int jj = 0; jj < 4; jj++) {
        int c = t + jj * 128;
        float acc = 0.f;
        #pragma unroll 8
        for (int hd = 0; hd < 64; hd++)
            acc += Qs[hd] * Wk[(size_t)(h * 64 + hd) * D_MODEL + c];
        g_QW[r * D_MODEL + c] = tf32r(acc * SCALE);
    }
    if (t == 0) {
        float acc = 0.f;
        for (int hd = 0; hd < 64; hd++)
            acc += Qs[hd] * bk[h * 64 + hd];
        g_qb[r] = acc * SCALE;
    }
}

// ---------------------------------------------------------------------------
// B: per-batch attention with tf32 mma. grid=2048, block=256, smem ~180KB.
// ---------------------------------------------------------------------------
__global__ __launch_bounds__(256, 1)
void attn_kernel(const float* __restrict__ enc,
                 const int* __restrict__ valid,
                 const float* __restrict__ dist,
                 const float* __restrict__ cs_ptr) {
    extern __shared__ float sm[];
    float* enc_s  = sm;                       // 64*516
    float* qwch   = enc_s + 64 * EP;          // 64*132
    float* P_s    = qwch + 64 * QP;           // 64*68
    float* bias_s = P_s + 64 * PP;            // 64
    float* keep_s = bias_s + 64;              // 64
    float* qb_s   = keep_s + 64;              // 64
    float* any_s  = qb_s + 64;                // 4

    const int b = blockIdx.x, t = threadIdx.x;
    const int w = t >> 5, l = t & 31, g = l >> 2, tg = l & 3;
    const float cs = cs_ptr[0];

    // ---- stage enc (tf32-rounded) + per-k bias/mask ----
    const float4* encg = (const float4*)(enc + (size_t)b * K_NBR * D_MODEL);
    #pragma unroll 1
    for (int i = t; i < 64 * 128; i += 256) {
        int k = i >> 7, c4 = i & 127;
        *(float4*)&enc_s[k * EP + c4 * 4] = tf32r4(encg[i]);
    }
    if (t < 64) {
        bias_s[t] = dist[b * K_NBR + t] * cs;
        keep_s[t] = (valid[b * K_NBR + t] != 0) ? 1.f : 0.f;
        qb_s[t] = g_qb[t];
    }
    if (t == 0) any_s[0] = 0.f;
    __syncthreads();
    if (t < 64 && keep_s[t] != 0.f) any_s[0] = 1.f;   // benign same-value race

    // ---- logits: L[64 hs x 64 k], A=QW (chunked), B=enc_s ----
    const int mi = w >> 1, nj0 = (w & 1) * 4;
    float accL[4][4];
    #pragma unroll
    for (int j = 0; j < 4; j++)
        #pragma unroll
        for (int e = 0; e < 4; e++) accL[j][e] = 0.f;

    #pragma unroll 1
    for (int ch = 0; ch < 4; ch++) {
        #pragma unroll 1
        for (int i = t; i < 64 * 32; i += 256) {
            int r = i >> 5, c = i & 31;
            *(float4*)&qwch[r * QP + c * 4] =
                *(const float4*)&g_QW[r * D_MODEL + ch * 128 + c * 4];
        }
        __syncthreads();
        #pragma unroll 2
        for (int ks = 0; ks < 16; ks++) {
            int kb = ks * 8;
            u32 a[4];
            a[0] = __float_as_uint(qwch[(mi * 16 + g) * QP + kb + tg]);
            a[1] = __float_as_uint(qwch[(mi * 16 + g + 8) * QP + kb + tg]);
            a[2] = __float_as_uint(qwch[(mi * 16 + g) * QP + kb + tg + 4]);
            a[3] = __float_as_uint(qwch[(mi * 16 + g + 8) * QP + kb + tg + 4]);
            #pragma unroll
            for (int j = 0; j < 4; j++) {
                const float* Bb = enc_s + ((nj0 + j) * 8 + g) * EP + ch * 128 + kb;
                u32 bb_[2] = {__float_as_uint(Bb[tg]), __float_as_uint(Bb[tg + 4])};
                mma8(accL[j], a, bb_);
            }
        }
        __syncthreads();
    }
    // store logits with bias + mask
    {
        int r0 = mi * 16 + g, r1 = r0 + 8;
        float q0 = qb_s[r0], q1 = qb_s[r1];
        #pragma unroll
        for (int j = 0; j < 4; j++) {
            int c0 = (nj0 + j) * 8 + 2 * tg, c1 = c0 + 1;
            float bi0 = bias_s[c0], bi1 = bias_s[c1];
            bool k0 = keep_s[c0] != 0.f, k1 = keep_s[c1] != 0.f;
            P_s[r0 * PP + c0] = k0 ? accL[j][0] + q0 + bi0 : -10000.0f;
            P_s[r0 * PP + c1] = k1 ? accL[j][1] + q0 + bi1 : -10000.0f;
            P_s[r1 * PP + c0] = k0 ? accL[j][2] + q1 + bi0 : -10000.0f;
            P_s[r1 * PP + c1] = k1 ? accL[j][3] + q1 + bi1 : -10000.0f;
        }
    }
    __syncthreads();

    // ---- softmax (8 rows per warp), store tf32-rounded probs ----
    #pragma unroll 1
    for (int rr = 0; rr < 8; rr++) {
        int hs = w * 8 + rr;
        float v0 = P_s[hs * PP + l], v1 = P_s[hs * PP + l + 32];
        float m = fmaxf(v0, v1);
        #pragma unroll
        for (int o = 16; o > 0; o >>= 1) m = fmaxf(m, __shfl_xor_sync(~0u, m, o));
        float e0 = __expf(v0 - m), e1 = __expf(v1 - m);
        float ssum = e0 + e1;
        #pragma unroll
        for (int o = 16; o > 0; o >>= 1) ssum += __shfl_xor_sync(~0u, ssum, o);
        float inv = 1.f / ssum;
        P_s[hs * PP + l] = tf32r(e0 * inv);
        P_s[hs * PP + l + 32] = tf32r(e1 * inv);
    }
    __syncthreads();

    // ---- ctx = P @ enc : M=64, N=512, K=64 ; store straight to gmem ----
    const int mg = w >> 2, ng = w & 3;
    float* cg = g_ctx + (size_t)b * SH * D_MODEL;
    #pragma unroll 1
    for (int p = 0; p < 2; p++) {
        float acc[2][8][4];
        #pragma unroll
        for (int mt = 0; mt < 2; mt++)
            #pragma unroll
            for (int nt = 0; nt < 8; nt++)
                #pragma unroll
                for (int e = 0; e < 4; e++) acc[mt][nt][e] = 0.f;
        #pragma unroll 2
        for (int ks = 0; ks < 8; ks++) {
            int kb = ks * 8;
            u32 a[2][4];
            #pragma unroll
            for (int mt = 0; mt < 2; mt++) {
                int rb = (mg * 2 + mt) * 16;
                a[mt][0] = __float_as_uint(P_s[(rb + g) * PP + kb + tg]);
                a[mt][1] = __float_as_uint(P_s[(rb + g + 8) * PP + kb + tg]);
                a[mt][2] = __float_as_uint(P_s[(rb + g) * PP + kb + tg + 4]);
                a[mt][3] = __float_as_uint(P_s[(rb + g + 8) * PP + kb + tg + 4]);
            }
            #pragma unroll
            for (int nt = 0; nt < 8; nt++) {
                int ncol = (ng * 16 + p * 8 + nt) * 8 + g;
                u32 bb_[2] = {__float_as_uint(enc_s[(kb + tg) * EP + ncol]),
                              __float_as_uint(enc_s[(kb + tg + 4) * EP + ncol])};
                mma8(acc[0][nt], a[0], bb_);
                mma8(acc[1][nt], a[1], bb_);
            }
        }
        #pragma unroll
        for (int mt = 0; mt < 2; mt++) {
            int r0 = (mg * 2 + mt) * 16 + g;
            #pragma unroll
            for (int nt = 0; nt < 8; nt++) {
                int c0 = (ng * 16 + p * 8 + nt) * 8 + 2 * tg;
                *(float2*)&cg[(size_t)r0 * D_MODEL + c0] =
                    make_float2(acc[mt][nt][0], acc[mt][nt][1]);
                *(float2*)&cg[(size_t)(r0 + 8) * D_MODEL + c0] =
                    make_float2(acc[mt][nt][2], acc[mt][nt][3]);
            }
        }
    }
    if (t == 0) g_anyvalid[b] = any_s[0];
}

// ---------------------------------------------------------------------------
// C: 64 (b,s)-rows per CTA. stage1: tmp2 = per-head ctx @ Wv_h^T + bv (mma);
//    stage2: out = tmp2 @ Wo^T (mma, acc in regs); then LN + mask.
// grid=256, block=256, smem ~223KB.
// ---------------------------------------------------------------------------
__global__ __launch_bounds__(256, 1)
void out_kernel(const float* __restrict__ Wv, const float* __restrict__ bv,
                const float* __restrict__ Wo, const float* __restrict__ bo,
                const float* __restrict__ shift,
                const float* __restrict__ lnw, const float* __restrict__ lnb,
                float* __restrict__ out) {
    extern __shared__ float sm[];
    float* tmp2    = sm;                      // 64*516 = 33024
    float* buf     = tmp2 + 64 * EP;          // 17408 (stage1: 2x(64*68) a + 2x(64*68) w; stage2: 128*132)
    float* bo_s    = buf + 17408;             // 512
    float* bv_s    = bo_s + 512;              // 512
    float* lnw_s   = bv_s + 512;              // 512
    float* lnb_s   = lnw_s + 512;             // 512
    float* shift_s = lnb_s + 512;             // 8*512
    float* rsum    = shift_s + 4096;          // 64*4
    float* rsq     = rsum + 256;              // 64*4

    const int t = threadIdx.x;
    const int w = t >> 5, l = t & 31, g = l >> 2, tg = l & 3;
    const int rowbase = blockIdx.x * ROWB;

    #pragma unroll 1
    for (int i = t; i < 512; i += 256) {
        bo_s[i] = bo[i]; bv_s[i] = bv[i]; lnw_s[i] = lnw[i]; lnb_s[i] = lnb[i];
    }
    #pragma unroll 1
    for (int i = t; i < 4096; i += 256) shift_s[i] = shift[i];

    // ================= stage 1: tmp2 = ctx @ Wv_h^T + bv =================
    // 2 heads staged per iteration; 4 warps per head; warp tile 2m x 4n.
    const int hh  = w >> 2;          // staged-head slot (0/1)
    const int ww  = w & 3;
    const int mgs = ww >> 1, ngg = ww & 1;
    float* abuf  = buf;              // [slot][64][68]
    float* wvbuf = buf + 2 * 64 * PP;

    #pragma unroll 1
    for (int it = 0; it < 4; it++) {
        float acc[2][4][4];
        #pragma unroll
        for (int mt = 0; mt < 2; mt++)
            #pragma unroll
            for (int nt = 0; nt < 4; nt++)
                #pragma unroll
                for (int e = 0; e < 4; e++) acc[mt][nt][e] = 0.f;

        #pragma unroll 1
        for (int kc = 0; kc < 8; kc++) {
            __syncthreads();   // previous chunk's reads complete
            #pragma unroll 1
            for (int i = t; i < 2048; i += 256) {
                int slot = i >> 10, rem = i & 1023, r = rem >> 4, c4 = rem & 15;
                int h = it * 2 + slot;
                int gr = rowbase + r, bb = gr >> 3, ss = gr & 7;
                float4 v = *(const float4*)
                    &g_ctx[((size_t)bb * SH + h * 8 + ss) * D_MODEL + kc * 64 + c4 * 4];
                *(float4*)&abuf[slot * 64 * PP + r * PP + c4 * 4] = tf32r4(v);
            }
            #pragma unroll 1
            for (int i = t; i < 2048; i += 256) {
                int slot = i >> 10, rem = i & 1023, r = rem >> 4, c4 = rem & 15;
                int h = it * 2 + slot;
                float4 v = *(const float4*)
                    &Wv[((size_t)h * 64 + r) * D_MODEL + kc * 64 + c4 * 4];
                *(float4*)&wvbuf[slot * 64 * PP + r * PP + c4 * 4] = tf32r4(v);
            }
            __syncthreads();
            const float* Ab = abuf + hh * 64 * PP;
            const float* Wb = wvbuf + hh * 64 * PP;
            #pragma unroll 2
            for (int ks = 0; ks < 8; ks++) {
                int kb = ks * 8;
                u32 a[2][4];
                #pragma unroll
                for (int mt = 0; mt < 2; mt++) {
                    int rb = (mgs * 2 + mt) * 16;
                    a[mt][0] = __float_as_uint(Ab[(rb + g) * PP + kb + tg]);
                    a[mt][1] = __float_as_uint(Ab[(rb + g + 8) * PP + kb + tg]);
                    a[mt][2] = __float_as_uint(Ab[(rb + g) * PP + kb + tg + 4]);
                    a[mt][3] = __float_as_uint(Ab[(rb + g + 8) * PP + kb + tg + 4]);
                }
                #pragma unroll
                for (int nt = 0; nt < 4; nt++) {
                    int nrow = (ngg * 4 + nt) * 8 + g;
                    u32 bb_[2] = {__float_as_uint(Wb[nrow * PP + kb + tg]),
                                  __float_as_uint(Wb[nrow * PP + kb + tg + 4])};
                    mma8(acc[0][nt], a[0], bb_);
                    mma8(acc[1][nt], a[1], bb_);
                }
            }
        }
        // write this head's tmp2 block (+bv, tf32-rounded)
        int h = it * 2 + hh;
        #pragma unroll
        for (int mt = 0; mt < 2; mt++) {
            int r0 = (mgs * 2 + mt) * 16 + g;
            #pragma unroll
            for (int nt = 0; nt < 4; nt++) {
                int c0 = h * 64 + (ngg * 4 + nt) * 8 + 2 * tg;
                tmp2[r0 * EP + c0]           = tf32r(acc[mt][nt][0] + bv_s[c0]);
                tmp2[r0 * EP + c0 + 1]       = tf32r(acc[mt][nt][1] + bv_s[c0 + 1]);
                tmp2[(r0 + 8) * EP + c0]     = tf32r(acc[mt][nt][2] + bv_s[c0]);
                tmp2[(r0 + 8) * EP + c0 + 1] = tf32r(acc[mt][nt][3] + bv_s[c0 + 1]);
            }
        }
    }

    // ================= stage 2: out = tmp2 @ Wo^T (acc in regs) ==========
    const int mg2 = w >> 2, ng2 = w & 3;   // warp tile 2m x 4n per n-block
    float acc2[4][2][4][4];
    #pragma unroll
    for (int nb = 0; nb < 4; nb++)
        #pragma unroll
        for (int mt = 0; mt < 2; mt++)
            #pragma unroll
            for (int nt = 0; nt < 4; nt++)
                #pragma unroll
                for (int e = 0; e < 4; e++) acc2[nb][mt][nt][e] = 0.f;

    #pragma unroll
    for (int nb = 0; nb < 4; nb++) {
        #pragma unroll 1
        for (int kc = 0; kc < 4; kc++) {
            __syncthreads();
            #pragma unroll 1
            for (int i = t; i < 4096; i += 256) {
                int r = i >> 5, c4 = i & 31;
                float4 v = *(const float4*)
                    &Wo[((size_t)(nb * 128 + r)) * D_MODEL + kc * 128 + c4 * 4];
                *(float4*)&buf[r * QP + c4 * 4] = tf32r4(v);
            }
            __syncthreads();
            #pragma unroll 2
            for (int ks = 0; ks < 16; ks++) {
                int kb = ks * 8;
                u32 a[2][4];
                #pragma unroll
                for (int mt = 0; mt < 2; mt++) {
                    int rb = (mg2 * 2 + mt) * 16;
                    const float* Ab = tmp2 + kc * 128 + kb;
                    a[mt][0] = __float_as_uint(Ab[(rb + g) * EP + tg]);
                    a[mt][1] = __float_as_uint(Ab[(rb + g + 8) * EP + tg]);
                    a[mt][2] = __float_as_uint(Ab[(rb + g) * EP + tg + 4]);
                    a[mt][3] = __float_as_uint(Ab[(rb + g + 8) * EP + tg + 4]);
                }
                #pragma unroll
                for (int nt = 0; nt < 4; nt++) {
                    int nrow = (ng2 * 4 + nt) * 8 + g;
                    u32 bb_[2] = {__float_as_uint(buf[nrow * QP + kb + tg]),
                                  __float_as_uint(buf[nrow * QP + kb + tg + 4])};
                    mma8(acc2[nb][0][nt], a[0], bb_);
                    mma8(acc2[nb][1][nt], a[1], bb_);
                }
            }
        }
    }

    // ================= LayerNorm + residual + mask =======================
    // x = out + bo + shift; rows owned: (mg2*2+mt)*16 + g (+8); ss = g.
    const int ssg = g & 7;
    float psum[2][2] = {{0.f, 0.f}, {0.f, 0.f}};
    float psq[2][2]  = {{0.f, 0.f}, {0.f, 0.f}};
    #pragma unroll
    for (int nb = 0; nb < 4; nb++)
        #pragma unroll
        for (int mt = 0; mt < 2; mt++)
            #pragma unroll
            for (int nt = 0; nt < 4; nt++) {
                int c0 = nb * 128 + (ng2 * 4 + nt) * 8 + 2 * tg;
                float add0 = bo_s[c0] + shift_s[ssg * 512 + c0];
                float add1 = bo_s[c0 + 1] + shift_s[ssg * 512 + c0 + 1];
                float x0 = acc2[nb][mt][nt][0] + add0;
                float x1 = acc2[nb][mt][nt][1] + add1;
                float x2 = acc2[nb][mt][nt][2] + add0;
                float x3 = acc2[nb][mt][nt][3] + add1;
                acc2[nb][mt][nt][0] = x0; acc2[nb][mt][nt][1] = x1;
                acc2[nb][mt][nt][2] = x2; acc2[nb][mt][nt][3] = x3;
                psum[mt][0] += x0 + x1; psq[mt][0] += x0 * x0 + x1 * x1;
                psum[mt][1] += x2 + x3; psq[mt][1] += x2 * x2 + x3 * x3;
            }
    #pragma unroll
    for (int mt = 0; mt < 2; mt++)
        #pragma unroll
        for (int hf = 0; hf < 2; hf++) {
            #pragma unroll
            for (int o = 1; o <= 2; o <<= 1) {
                psum[mt][hf] += __shfl_xor_sync(~0u, psum[mt][hf], o);
                psq[mt][hf]  += __shfl_xor_sync(~0u, psq[mt][hf], o);
            }
        }
    if (tg == 0) {
        #pragma unroll
        for (int mt = 0; mt < 2; mt++)
            #pragma unroll
            for (int hf = 0; hf < 2; hf++) {
                int row = (mg2 * 2 + mt) * 16 + g + hf * 8;
                rsum[row * 4 + ng2] = psum[mt][hf];
                rsq[row * 4 + ng2]  = psq[mt][hf];
            }
    }
    __syncthreads();

    float mu[2][2], rstd[2][2], av[2][2];
    #pragma unroll
    for (int mt = 0; mt < 2; mt++)
        #pragma unroll
        for (int hf = 0; hf < 2; hf++) {
            int row = (mg2 * 2 + mt) * 16 + g + hf * 8;
            float s  = rsum[row * 4] + rsum[row * 4 + 1] + rsum[row * 4 + 2] + rsum[row * 4 + 3];
            float sq = rsq[row * 4] + rsq[row * 4 + 1] + rsq[row * 4 + 2] + rsq[row * 4 + 3];
            float m = s * (1.f / D_MODEL);
            mu[mt][hf] = m;
            rstd[mt][hf] = rsqrtf(sq * (1.f / D_MODEL) - m * m + LN_EPS);
            av[mt][hf] = g_anyvalid[(rowbase + row) >> 3];
        }

    #pragma unroll
    for (int nb = 0; nb < 4; nb++)
        #pragma unroll
        for (int mt = 0; mt < 2; mt++)
            #pragma unroll
            for (int nt = 0; nt < 4; nt++) {
                int c0 = nb * 128 + (ng2 * 4 + nt) * 8 + 2 * tg;
                float w0 = lnw_s[c0], w1 = lnw_s[c0 + 1];
                float b0v = lnb_s[c0], b1v = lnb_s[c0 + 1];
                int r0 = (mg2 * 2 + mt) * 16 + g;
                float y0 = ((acc2[nb][mt][nt][0] - mu[mt][0]) * rstd[mt][0] * w0 + b0v) * av[mt][0];
                float y1 = ((acc2[nb][mt][nt][1] - mu[mt][0]) * rstd[mt][0] * w1 + b1v) * av[mt][0];
                float y2 = ((acc2[nb][mt][nt][2] - mu[mt][1]) * rstd[mt][1] * w0 + b0v) * av[mt][1];
                float y3 = ((acc2[nb][mt][nt][3] - mu[mt][1]) * rstd[mt][1] * w1 + b1v) * av[mt][1];
                *(float2*)&out[(size_t)(rowbase + r0) * D_MODEL + c0] = make_float2(y0, y1);
                *(float2*)&out[(size_t)(rowbase + r0 + 8) * D_MODEL + c0] = make_float2(y2, y3);
            }
}

// ---------------------------------------------------------------------------
extern "C" void kernel_launch(void* const* d_in, const int* in_sizes, int n_in,
                              void* d_out, int out_size) {
    (void)in_sizes; (void)n_in; (void)out_size;
    const float* enc   = (const float*)d_in[0];
    const int*   valid = (const int*)d_in[1];
    const float* dist  = (const float*)d_in[2];
    const float* shift = (const float*)d_in[3];
    const float* Wq    = (const float*)d_in[4];
    const float* bq    = (const float*)d_in[5];
    const float* Wk    = (const float*)d_in[6];
    const float* bk    = (const float*)d_in[7];
    const float* Wv    = (const float*)d_in[8];
    const float* bv    = (const float*)d_in[9];
    const float* Wo    = (const float*)d_in[10];
    const float* bo    = (const float*)d_in[11];
    const float* lnw   = (const float*)d_in[12];
    const float* lnb   = (const float*)d_in[13];
    const float* cs    = (const float*)d_in[14];

    const int smemB = (64 * EP + 64 * QP + 64 * PP + 4 * 64) * 4;
    const int smemC = (64 * EP + 17408 + 4 * 512 + 4096 + 2 * 256) * 4;
    cudaFuncSetAttribute(attn_kernel, cudaFuncAttributeMaxDynamicSharedMemorySize, smemB);
    cudaFuncSetAttribute(out_kernel,  cudaFuncAttributeMaxDynamicSharedMemorySize, smemC);

    qproj_kernel<<<(N_SHIFTS * D_MODEL + 127) / 128, 128>>>(shift, Wq, bq);
    qw_kernel<<<SH, 128>>>(Wk, bk);
    attn_kernel<<<B_SZ, 256, smemB>>>(enc, valid, dist, cs);
    out_kernel<<<(B_SZ * N_SHIFTS) / ROWB, 256, smemC>>>(Wv, bv, Wo, bo, shift,
                                                         lnw, lnb, (float*)d_out);
}

// round 14
// speedup vs baseline: 2.9025x; 1.5150x over previous
#include <cuda_runtime.h>

// ---------------------------------------------------------------------------
// ShiftSpecificCrossAttention — tf32 mma, 512-thread blocks (16 warps) for
// latency hiding (R10 profile: 8-warp version was issue-starved, occ 12%).
// ---------------------------------------------------------------------------

#define D_MODEL   512
#define N_SHIFTS  8
#define N_HEADS   8
#define B_SZ      2048
#define K_NBR     64
#define SH        64
#define SCALE     0.125f
#define LN_EPS    1e-5f

#define EP   516
#define QP   132
#define PP   68
#define ROWB 64

typedef unsigned int u32;

__device__ __forceinline__ float tf32r(float x) {
    float y; asm("cvt.rna.tf32.f32 %0, %1;" : "=f"(y) : "f"(x)); return y;
}
__device__ __forceinline__ float4 tf32r4(float4 v) {
    v.x = tf32r(v.x); v.y = tf32r(v.y); v.z = tf32r(v.z); v.w = tf32r(v.w);
    return v;
}
__device__ __forceinline__ void mma8(float* c, const u32* a, const u32* b) {
    asm volatile(
        "mma.sync.aligned.m16n8k8.row.col.f32.tf32.tf32.f32 "
        "{%0,%1,%2,%3},{%4,%5,%6,%7},{%8,%9},{%0,%1,%2,%3};"
        : "+f"(c[0]), "+f"(c[1]), "+f"(c[2]), "+f"(c[3])
        : "r"(a[0]), "r"(a[1]), "r"(a[2]), "r"(a[3]), "r"(b[0]), "r"(b[1]));
}

__device__ __align__(16) float g_Q[N_SHIFTS * D_MODEL];
__device__ __align__(16) float g_QW[SH * D_MODEL];
__device__ float g_qb[SH];
__device__ float g_anyvalid[B_SZ];
__device__ __align__(16) float g_ctx[(size_t)B_SZ * SH * D_MODEL];

// ---------------------------------------------------------------------------
__global__ void qproj_kernel(const float* __restrict__ shift,
                             const float* __restrict__ Wq,
                             const float* __restrict__ bq) {
    int gidx = blockIdx.x * blockDim.x + threadIdx.x;
    if (gidx >= N_SHIFTS * D_MODEL) return;
    int s = gidx / D_MODEL, i = gidx % D_MODEL;
    const float* sr = shift + s * D_MODEL;
    const float* wr = Wq + (size_t)i * D_MODEL;
    float a0 = 0.f, a1 = 0.f, a2 = 0.f, a3 = 0.f;
    #pragma unroll 4
    for (int d = 0; d < D_MODEL; d += 4) {
        a0 += sr[d + 0] * wr[d + 0];
        a1 += sr[d + 1] * wr[d + 1];
        a2 += sr[d + 2] * wr[d + 2];
        a3 += sr[d + 3] * wr[d + 3];
    }
    g_Q[gidx] = bq[i] + ((a0 + a1) + (a2 + a3));
}

// ---------------------------------------------------------------------------
__global__ void qw_kernel(const float* __restrict__ Wk,
                          const float* __restrict__ bk) {
    __shared__ float Qs[64];
    int r = blockIdx.x;
    int h = r / N_SHIFTS, s = r % N_SHIFTS;
    int t = threadIdx.x;
    if (t < 64) Qs[t] = g_Q[s * D_MODEL + h * 64 + t];
    __syncthreads();
    #pragma unroll
    for (int jj = 0; jj < 4; jj++) {
        int c = t + jj * 128;
        float acc = 0.f;
        #pragma unroll 8
        for (int hd = 0; hd < 64; hd++)
            acc += Qs[hd] * Wk[(size_t)(h * 64 + hd) * D_MODEL + c];
        g_QW[r * D_MODEL + c] = tf32r(acc * SCALE);
    }
    if (t == 0) {
        float acc = 0.f;
        for (int hd = 0; hd < 64; hd++)
            acc += Qs[hd] * bk[h * 64 + hd];
        g_qb[r] = acc * SCALE;
    }
}

// ---------------------------------------------------------------------------
// B: per-batch attention, 512 threads (16 warps). smem ~184KB, 1 CTA/SM.
// ---------------------------------------------------------------------------
__global__ __launch_bounds__(512, 1)
void attn_kernel(const float* __restrict__ enc,
                 const int* __restrict__ valid,
                 const float* __restrict__ dist,
                 const float* __restrict__ cs_ptr) {
    extern __shared__ float sm[];
    float* enc_s  = sm;                       // 64*516
    float* qwch   = enc_s + 64 * EP;          // 64*132
    float* P_s    = qwch + 64 * QP;           // 64*68
    float* bias_s = P_s + 64 * PP;            // 64
    float* keep_s = bias_s + 64;              // 64
    float* qb_s   = keep_s + 64;              // 64
    float* any_s  = qb_s + 64;                // 4

    const int b = blockIdx.x, t = threadIdx.x;
    const int w = t >> 5, l = t & 31, g = l >> 2, tg = l & 3;
    const float cs = cs_ptr[0];

    // ---- stage enc (tf32-rounded) + per-k bias/mask ----
    const float4* encg = (const float4*)(enc + (size_t)b * K_NBR * D_MODEL);
    #pragma unroll 1
    for (int i = t; i < 64 * 128; i += 512) {
        int k = i >> 7, c4 = i & 127;
        *(float4*)&enc_s[k * EP + c4 * 4] = tf32r4(encg[i]);
    }
    if (t < 64) {
        bias_s[t] = dist[b * K_NBR + t] * cs;
        keep_s[t] = (valid[b * K_NBR + t] != 0) ? 1.f : 0.f;
        qb_s[t] = g_qb[t];
    }
    if (t == 0) any_s[0] = 0.f;
    __syncthreads();
    if (t < 64 && keep_s[t] != 0.f) any_s[0] = 1.f;   // benign same-value race

    // ---- logits: 16 warps = 4m x 4n; each warp 16 rows x 16 cols ----
    const int mi = w >> 2, nj0 = (w & 3) * 2;
    float accL[2][4];
    #pragma unroll
    for (int j = 0; j < 2; j++)
        #pragma unroll
        for (int e = 0; e < 4; e++) accL[j][e] = 0.f;

    #pragma unroll 1
    for (int ch = 0; ch < 4; ch++) {
        #pragma unroll 1
        for (int i = t; i < 64 * 32; i += 512) {
            int r = i >> 5, c = i & 31;
            *(float4*)&qwch[r * QP + c * 4] =
                *(const float4*)&g_QW[r * D_MODEL + ch * 128 + c * 4];
        }
        __syncthreads();
        #pragma unroll 2
        for (int ks = 0; ks < 16; ks++) {
            int kb = ks * 8;
            u32 a[4];
            a[0] = __float_as_uint(qwch[(mi * 16 + g) * QP + kb + tg]);
            a[1] = __float_as_uint(qwch[(mi * 16 + g + 8) * QP + kb + tg]);
            a[2] = __float_as_uint(qwch[(mi * 16 + g) * QP + kb + tg + 4]);
            a[3] = __float_as_uint(qwch[(mi * 16 + g + 8) * QP + kb + tg + 4]);
            #pragma unroll
            for (int j = 0; j < 2; j++) {
                const float* Bb = enc_s + ((nj0 + j) * 8 + g) * EP + ch * 128 + kb;
                u32 bb_[2] = {__float_as_uint(Bb[tg]), __float_as_uint(Bb[tg + 4])};
                mma8(accL[j], a, bb_);
            }
        }
        __syncthreads();
    }
    // store logits with bias + mask
    {
        int r0 = mi * 16 + g, r1 = r0 + 8;
        float q0 = qb_s[r0], q1 = qb_s[r1];
        #pragma unroll
        for (int j = 0; j < 2; j++) {
            int c0 = (nj0 + j) * 8 + 2 * tg, c1 = c0 + 1;
            float bi0 = bias_s[c0], bi1 = bias_s[c1];
            bool k0 = keep_s[c0] != 0.f, k1 = keep_s[c1] != 0.f;
            P_s[r0 * PP + c0] = k0 ? accL[j][0] + q0 + bi0 : -10000.0f;
            P_s[r0 * PP + c1] = k1 ? accL[j][1] + q0 + bi1 : -10000.0f;
            P_s[r1 * PP + c0] = k0 ? accL[j][2] + q1 + bi0 : -10000.0f;
            P_s[r1 * PP + c1] = k1 ? accL[j][3] + q1 + bi1 : -10000.0f;
        }
    }
    __syncthreads();

    // ---- softmax (4 rows per warp), store tf32-rounded probs ----
    #pragma unroll 1
    for (int rr = 0; rr < 4; rr++) {
        int hs = w * 4 + rr;
        float v0 = P_s[hs * PP + l], v1 = P_s[hs * PP + l + 32];
        float m = fmaxf(v0, v1);
        #pragma unroll
        for (int o = 16; o > 0; o >>= 1) m = fmaxf(m, __shfl_xor_sync(~0u, m, o));
        float e0 = __expf(v0 - m), e1 = __expf(v1 - m);
        float ssum = e0 + e1;
        #pragma unroll
        for (int o = 16; o > 0; o >>= 1) ssum += __shfl_xor_sync(~0u, ssum, o);
        float inv = 1.f / ssum;
        P_s[hs * PP + l] = tf32r(e0 * inv);
        P_s[hs * PP + l + 32] = tf32r(e1 * inv);
    }
    __syncthreads();

    // ---- ctx = P @ enc : 16 warps = 2m x 8n-groups; warp = 32 rows x 64 cols
    const int mg = w >> 3, ng = w & 7;
    float* cg = g_ctx + (size_t)b * SH * D_MODEL;
    {
        float acc[2][8][4];
        #pragma unroll
        for (int mt = 0; mt < 2; mt++)
            #pragma unroll
            for (int nt = 0; nt < 8; nt++)
                #pragma unroll
                for (int e = 0; e < 4; e++) acc[mt][nt][e] = 0.f;
        #pragma unroll 2
        for (int ks = 0; ks < 8; ks++) {
            int kb = ks * 8;
            u32 a[2][4];
            #pragma unroll
            for (int mt = 0; mt < 2; mt++) {
                int rb = (mg * 2 + mt) * 16;
                a[mt][0] = __float_as_uint(P_s[(rb + g) * PP + kb + tg]);
                a[mt][1] = __float_as_uint(P_s[(rb + g + 8) * PP + kb + tg]);
                a[mt][2] = __float_as_uint(P_s[(rb + g) * PP + kb + tg + 4]);
                a[mt][3] = __float_as_uint(P_s[(rb + g + 8) * PP + kb + tg + 4]);
            }
            #pragma unroll
            for (int nt = 0; nt < 8; nt++) {
                int ncol = (ng * 8 + nt) * 8 + g;
                u32 bb_[2] = {__float_as_uint(enc_s[(kb + tg) * EP + ncol]),
                              __float_as_uint(enc_s[(kb + tg + 4) * EP + ncol])};
                mma8(acc[0][nt], a[0], bb_);
                mma8(acc[1][nt], a[1], bb_);
            }
        }
        #pragma unroll
        for (int mt = 0; mt < 2; mt++) {
            int r0 = (mg * 2 + mt) * 16 + g;
            #pragma unroll
            for (int nt = 0; nt < 8; nt++) {
                int c0 = (ng * 8 + nt) * 8 + 2 * tg;
                *(float2*)&cg[(size_t)r0 * D_MODEL + c0] =
                    make_float2(acc[mt][nt][0], acc[mt][nt][1]);
                *(float2*)&cg[(size_t)(r0 + 8) * D_MODEL + c0] =
                    make_float2(acc[mt][nt][2], acc[mt][nt][3]);
            }
        }
    }
    if (t == 0) g_anyvalid[b] = any_s[0];
}

// ---------------------------------------------------------------------------
// C: 64 rows per CTA, 512 threads (16 warps). smem ~223KB, 1 CTA/SM.
// ---------------------------------------------------------------------------
__global__ __launch_bounds__(512, 1)
void out_kernel(const float* __restrict__ Wv, const float* __restrict__ bv,
                const float* __restrict__ Wo, const float* __restrict__ bo,
                const float* __restrict__ shift,
                const float* __restrict__ lnw, const float* __restrict__ lnb,
                float* __restrict__ out) {
    extern __shared__ float sm[];
    float* tmp2    = sm;                      // 64*516
    float* buf     = tmp2 + 64 * EP;          // 17408
    float* bo_s    = buf + 17408;             // 512
    float* bv_s    = bo_s + 512;              // 512
    float* lnw_s   = bv_s + 512;              // 512
    float* lnb_s   = lnw_s + 512;             // 512
    float* shift_s = lnb_s + 512;             // 4096
    float* rsum    = shift_s + 4096;          // 256
    float* rsq     = rsum + 256;              // 256

    const int t = threadIdx.x;
    const int w = t >> 5, l = t & 31, g = l >> 2, tg = l & 3;
    const int rowbase = blockIdx.x * ROWB;

    #pragma unroll 1
    for (int i = t; i < 512; i += 512) {
        bo_s[i] = bo[i]; bv_s[i] = bv[i]; lnw_s[i] = lnw[i]; lnb_s[i] = lnb[i];
    }
    #pragma unroll 1
    for (int i = t; i < 4096; i += 512) shift_s[i] = shift[i];

    // ================= stage 1: tmp2 = ctx @ Wv_h^T + bv =================
    // 2 heads staged per iteration; 8 warps per head; warp tile 2m x 2n.
    const int hh  = w >> 3;          // staged-head slot (0/1)
    const int ww  = w & 7;
    const int mgs = ww >> 2, ngg = ww & 3;
    float* abuf  = buf;              // [slot][64][68]
    float* wvbuf = buf + 2 * 64 * PP;

    #pragma unroll 1
    for (int it = 0; it < 4; it++) {
        float acc[2][2][4];
        #pragma unroll
        for (int mt = 0; mt < 2; mt++)
            #pragma unroll
            for (int nt = 0; nt < 2; nt++)
                #pragma unroll
                for (int e = 0; e < 4; e++) acc[mt][nt][e] = 0.f;

        #pragma unroll 1
        for (int kc = 0; kc < 8; kc++) {
            __syncthreads();   // previous chunk's reads complete
            #pragma unroll 1
            for (int i = t; i < 2048; i += 512) {
                int slot = i >> 10, rem = i & 1023, r = rem >> 4, c4 = rem & 15;
                int h = it * 2 + slot;
                int gr = rowbase + r, bb = gr >> 3, ss = gr & 7;
                float4 v = *(const float4*)
                    &g_ctx[((size_t)bb * SH + h * 8 + ss) * D_MODEL + kc * 64 + c4 * 4];
                *(float4*)&abuf[slot * 64 * PP + r * PP + c4 * 4] = tf32r4(v);
            }
            #pragma unroll 1
            for (int i = t; i < 2048; i += 512) {
                int slot = i >> 10, rem = i & 1023, r = rem >> 4, c4 = rem & 15;
                int h = it * 2 + slot;
                float4 v = *(const float4*)
                    &Wv[((size_t)h * 64 + r) * D_MODEL + kc * 64 + c4 * 4];
                *(float4*)&wvbuf[slot * 64 * PP + r * PP + c4 * 4] = tf32r4(v);
            }
            __syncthreads();
            const float* Ab = abuf + hh * 64 * PP;
            const float* Wb = wvbuf + hh * 64 * PP;
            #pragma unroll 2
            for (int ks = 0; ks < 8; ks++) {
                int kb = ks * 8;
                u32 a[2][4];
                #pragma unroll
                for (int mt = 0; mt < 2; mt++) {
                    int rb = (mgs * 2 + mt) * 16;
                    a[mt][0] = __float_as_uint(Ab[(rb + g) * PP + kb + tg]);
                    a[mt][1] = __float_as_uint(Ab[(rb + g + 8) * PP + kb + tg]);
                    a[mt][2] = __float_as_uint(Ab[(rb + g) * PP + kb + tg + 4]);
                    a[mt][3] = __float_as_uint(Ab[(rb + g + 8) * PP + kb + tg + 4]);
                }
                #pragma unroll
                for (int nt = 0; nt < 2; nt++) {
                    int nrow = (ngg * 2 + nt) * 8 + g;
                    u32 bb_[2] = {__float_as_uint(Wb[nrow * PP + kb + tg]),
                                  __float_as_uint(Wb[nrow * PP + kb + tg + 4])};
                    mma8(acc[0][nt], a[0], bb_);
                    mma8(acc[1][nt], a[1], bb_);
                }
            }
        }
        // write this head's tmp2 block (+bv, tf32-rounded)
        int h = it * 2 + hh;
        #pragma unroll
        for (int mt = 0; mt < 2; mt++) {
            int r0 = (mgs * 2 + mt) * 16 + g;
            #pragma unroll
            for (int nt = 0; nt < 2; nt++) {
                int c0 = h * 64 + (ngg * 2 + nt) * 8 + 2 * tg;
                tmp2[r0 * EP + c0]           = tf32r(acc[mt][nt][0] + bv_s[c0]);
                tmp2[r0 * EP + c0 + 1]       = tf32r(acc[mt][nt][1] + bv_s[c0 + 1]);
                tmp2[(r0 + 8) * EP + c0]     = tf32r(acc[mt][nt][2] + bv_s[c0]);
                tmp2[(r0 + 8) * EP + c0 + 1] = tf32r(acc[mt][nt][3] + bv_s[c0 + 1]);
            }
        }
    }

    // ================= stage 2: out = tmp2 @ Wo^T (acc in regs) ==========
    // 16 warps = 4m x 4n-quarters; warp = 16 rows x 128 cols (32 per nb).
    const int mg2 = w >> 2, ng2 = w & 3;
    float acc2[4][4][4];
    #pragma unroll
    for (int nb = 0; nb < 4; nb++)
        #pragma unroll
        for (int nt = 0; nt < 4; nt++)
            #pragma unroll
            for (int e = 0; e < 4; e++) acc2[nb][nt][e] = 0.f;

    #pragma unroll
    for (int nb = 0; nb < 4; nb++) {
        #pragma unroll 1
        for (int kc = 0; kc < 4; kc++) {
            __syncthreads();
            #pragma unroll 1
            for (int i = t; i < 4096; i += 512) {
                int r = i >> 5, c4 = i & 31;
                float4 v = *(const float4*)
                    &Wo[((size_t)(nb * 128 + r)) * D_MODEL + kc * 128 + c4 * 4];
                *(float4*)&buf[r * QP + c4 * 4] = tf32r4(v);
            }
            __syncthreads();
            #pragma unroll 2
            for (int ks = 0; ks < 16; ks++) {
                int kb = ks * 8;
                u32 a[4];
                {
                    int rb = mg2 * 16;
                    const float* Ab = tmp2 + kc * 128 + kb;
                    a[0] = __float_as_uint(Ab[(rb + g) * EP + tg]);
                    a[1] = __float_as_uint(Ab[(rb + g + 8) * EP + tg]);
                    a[2] = __float_as_uint(Ab[(rb + g) * EP + tg + 4]);
                    a[3] = __float_as_uint(Ab[(rb + g + 8) * EP + tg + 4]);
                }
                #pragma unroll
                for (int nt = 0; nt < 4; nt++) {
                    int nrow = (ng2 * 4 + nt) * 8 + g;
                    u32 bb_[2] = {__float_as_uint(buf[nrow * QP + kb + tg]),
                                  __float_as_uint(buf[nrow * QP + kb + tg + 4])};
                    mma8(acc2[nb][nt], a, bb_);
                }
            }
        }
    }

    // ================= LayerNorm + residual + mask =======================
    // rows owned: mg2*16 + g (+8); ss = g (rowbase,mg2*16,8 all ≡0 mod 8).
    const int ssg = g & 7;
    float psum[2] = {0.f, 0.f};
    float psq[2]  = {0.f, 0.f};
    #pragma unroll
    for (int nb = 0; nb < 4; nb++)
        #pragma unroll
        for (int nt = 0; nt < 4; nt++) {
            int c0 = nb * 128 + (ng2 * 4 + nt) * 8 + 2 * tg;
            float add0 = bo_s[c0] + shift_s[ssg * 512 + c0];
            float add1 = bo_s[c0 + 1] + shift_s[ssg * 512 + c0 + 1];
            float x0 = acc2[nb][nt][0] + add0;
            float x1 = acc2[nb][nt][1] + add1;
            float x2 = acc2[nb][nt][2] + add0;
            float x3 = acc2[nb][nt][3] + add1;
            acc2[nb][nt][0] = x0; acc2[nb][nt][1] = x1;
            acc2[nb][nt][2] = x2; acc2[nb][nt][3] = x3;
            psum[0] += x0 + x1; psq[0] += x0 * x0 + x1 * x1;
            psum[1] += x2 + x3; psq[1] += x2 * x2 + x3 * x3;
        }
    #pragma unroll
    for (int hf = 0; hf < 2; hf++) {
        #pragma unroll
        for (int o = 1; o <= 2; o <<= 1) {
            psum[hf] += __shfl_xor_sync(~0u, psum[hf], o);
            psq[hf]  += __shfl_xor_sync(~0u, psq[hf], o);
        }
    }
    if (tg == 0) {
        #pragma unroll
        for (int hf = 0; hf < 2; hf++) {
            int row = mg2 * 16 + g + hf * 8;
            rsum[row * 4 + ng2] = psum[hf];
            rsq[row * 4 + ng2]  = psq[hf];
        }
    }
    __syncthreads();

    float mu[2], rstd[2], av[2];
    #pragma unroll
    for (int hf = 0; hf < 2; hf++) {
        int row = mg2 * 16 + g + hf * 8;
        float s  = rsum[row * 4] + rsum[row * 4 + 1] + rsum[row * 4 + 2] + rsum[row * 4 + 3];
        float sq = rsq[row * 4] + rsq[row * 4 + 1] + rsq[row * 4 + 2] + rsq[row * 4 + 3];
        float m = s * (1.f / D_MODEL);
        mu[hf] = m;
        rstd[hf] = rsqrtf(sq * (1.f / D_MODEL) - m * m + LN_EPS);
        av[hf] = g_anyvalid[(rowbase + row) >> 3];
    }

    #pragma unroll
    for (int nb = 0; nb < 4; nb++)
        #pragma unroll
        for (int nt = 0; nt < 4; nt++) {
            int c0 = nb * 128 + (ng2 * 4 + nt) * 8 + 2 * tg;
            float w0 = lnw_s[c0], w1 = lnw_s[c0 + 1];
            float b0v = lnb_s[c0], b1v = lnb_s[c0 + 1];
            int r0 = mg2 * 16 + g;
            float y0 = ((acc2[nb][nt][0] - mu[0]) * rstd[0] * w0 + b0v) * av[0];
            float y1 = ((acc2[nb][nt][1] - mu[0]) * rstd[0] * w1 + b1v) * av[0];
            float y2 = ((acc2[nb][nt][2] - mu[1]) * rstd[1] * w0 + b0v) * av[1];
            float y3 = ((acc2[nb][nt][3] - mu[1]) * rstd[1] * w1 + b1v) * av[1];
            *(float2*)&out[(size_t)(rowbase + r0) * D_MODEL + c0] = make_float2(y0, y1);
            *(float2*)&out[(size_t)(rowbase + r0 + 8) * D_MODEL + c0] = make_float2(y2, y3);
        }
}

// ---------------------------------------------------------------------------
extern "C" void kernel_launch(void* const* d_in, const int* in_sizes, int n_in,
                              void* d_out, int out_size) {
    (void)in_sizes; (void)n_in; (void)out_size;
    const float* enc   = (const float*)d_in[0];
    const int*   valid = (const int*)d_in[1];
    const float* dist  = (const float*)d_in[2];
    const float* shift = (const float*)d_in[3];
    const float* Wq    = (const float*)d_in[4];
    const float* bq    = (const float*)d_in[5];
    const float* Wk    = (const float*)d_in[6];
    const float* bk    = (const float*)d_in[7];
    const float* Wv    = (const float*)d_in[8];
    const float* bv    = (const float*)d_in[9];
    const float* Wo    = (const float*)d_in[10];
    const float* bo    = (const float*)d_in[11];
    const float* lnw   = (const float*)d_in[12];
    const float* lnb   = (const float*)d_in[13];
    const float* cs    = (const float*)d_in[14];

    const int smemB = (64 * EP + 64 * QP + 64 * PP + 4 * 64) * 4;
    const int smemC = (64 * EP + 17408 + 4 * 512 + 4096 + 2 * 256) * 4;
    cudaFuncSetAttribute(attn_kernel, cudaFuncAttributeMaxDynamicSharedMemorySize, smemB);
    cudaFuncSetAttribute(out_kernel,  cudaFuncAttributeMaxDynamicSharedMemorySize, smemC);

    qproj_kernel<<<(N_SHIFTS * D_MODEL + 127) / 128, 128>>>(shift, Wq, bq);
    qw_kernel<<<SH, 128>>>(Wk, bk);
    attn_kernel<<<B_SZ, 512, smemB>>>(enc, valid, dist, cs);
    out_kernel<<<(B_SZ * N_SHIFTS) / ROWB, 512, smemC>>>(Wv, bv, Wo, bo, shift,
                                                         lnw, lnb, (float*)d_out);
}